// round 15
// baseline (speedup 1.0000x reference)
#include <cuda_runtime.h>
#include <cuda_fp16.h>
#include <math.h>
#include <stdint.h>

#define Bsz   64
#define DL    1000
#define DIMG  2048
#define NF    36
#define DATT  512
#define DICT  9956
#define DICTP 9984
#define NSTEP 19
#define G4P   4096
#define K1P   2048
#define K2P   4096
#define KEP   1024

#define KC    64
#define APE   72
#define AOFF_LO 4608            /* 64*APE halfs */
#define BOFF    9216            /* 2*4608 halfs */
#define SMEM_L  92160           /* 4 stages * (9216+ 32*72) halfs * 2B */
#define SMEM_W4 82944           /* 3 stages * (9216+ 64*72) halfs * 2B */

// ---------------- device scratch (static; allocation-free) ----------------
__device__ __align__(16) __half d_W1hi[G4P * K1P];
__device__ __align__(16) __half d_W2hi[G4P * K2P];
__device__ __align__(16) __half d_Wehi[G4P * KEP];
__device__ __align__(16) __half d_Wphi[DICTP * KEP];
__device__ __align__(16) __half d_Waihi[DATT * DIMG];
__device__ __align__(16) __half d_W1vhi[G4P * DIMG];
__device__ __align__(16) __half d_feathi[NF * Bsz * DIMG];
__device__ __align__(16) __half d_featlo[NF * Bsz * DIMG];
__device__ __align__(16) __half d_embhi[NSTEP * Bsz * KEP];
__device__ __align__(16) __half d_emblo[NSTEP * Bsz * KEP];
__device__ __align__(16) __half d_h2hi[NSTEP * Bsz * KEP];
__device__ __align__(16) __half d_h2lo[NSTEP * Bsz * KEP];
__device__ __align__(16) __half d_x1hi[Bsz * K1P];
__device__ __align__(16) __half d_x1lo[Bsz * K1P];
__device__ __align__(16) __half d_x2hi[Bsz * K2P];
__device__ __align__(16) __half d_x2lo[Bsz * K2P];
__device__ __align__(16) __half d_vmhi[Bsz * DIMG];
__device__ __align__(16) __half d_vmlo[Bsz * DIMG];

__device__ __align__(16) float d_wc[NSTEP * Bsz * G4P];
__device__ __align__(16) float d_imgemb[Bsz * NF * DATT];
__device__ __align__(16) float d_base1p[Bsz * G4P];
__device__ __align__(16) float d_bias1p[G4P];
__device__ __align__(16) float d_bias2p[G4P];
__device__ __align__(16) float d_c1[Bsz * DL];
__device__ __align__(16) float d_c2[Bsz * DL];
__device__ __align__(16) float d_proj[Bsz * DATT];

__device__ __forceinline__ float sigf(float x) { return 1.f / (1.f + expf(-x)); }
__device__ __forceinline__ void split1(float v, __half& hi, __half& lo) {
    hi = __float2half(v);
    lo = __float2half(v - __half2float(hi));
}

__device__ __forceinline__ void ldsm_x4(uint32_t* r, const void* p) {
    uint32_t addr = (uint32_t)__cvta_generic_to_shared(p);
    asm volatile("ldmatrix.sync.aligned.m8n8.x4.shared.b16 {%0,%1,%2,%3}, [%4];"
                 : "=r"(r[0]), "=r"(r[1]), "=r"(r[2]), "=r"(r[3]) : "r"(addr));
}
__device__ __forceinline__ void ldsm_x2(uint32_t* r, const void* p) {
    uint32_t addr = (uint32_t)__cvta_generic_to_shared(p);
    asm volatile("ldmatrix.sync.aligned.m8n8.x2.shared.b16 {%0,%1}, [%2];"
                 : "=r"(r[0]), "=r"(r[1]) : "r"(addr));
}
__device__ __forceinline__ void mma16816(float* c, const uint32_t* a, const uint32_t* b) {
    asm volatile("mma.sync.aligned.m16n8k16.row.col.f32.f16.f16.f32 "
                 "{%0,%1,%2,%3}, {%4,%5,%6,%7}, {%8,%9}, {%0,%1,%2,%3};"
                 : "+f"(c[0]), "+f"(c[1]), "+f"(c[2]), "+f"(c[3])
                 : "r"(a[0]), "r"(a[1]), "r"(a[2]), "r"(a[3]), "r"(b[0]), "r"(b[1]));
}
__device__ __forceinline__ void cpasync16(__half* dst, const __half* src) {
    uint32_t d = (uint32_t)__cvta_generic_to_shared(dst);
    asm volatile("cp.async.cg.shared.global [%0], [%1], 16;" :: "r"(d), "l"(src));
}
#define CP_COMMIT() asm volatile("cp.async.commit_group;" ::: "memory")

// ---------------- shared GEMM core ----------------
template <int NT>
__device__ __forceinline__ void stage_copy(__half* sl, int tid,
                                           const __half* Ahi, const __half* Alo,
                                           const __half* Bh, int lda, int K,
                                           int gm0, int n0, int k0) {
#pragma unroll
    for (int i = 0; i < 4; i++) {
        int c = tid + i * 256;
        int arr = c >> 9, rem = c & 511;
        int row = rem >> 3, ch = rem & 7;
        const __half* src = (arr ? Alo : Ahi) + (size_t)(gm0 + row) * lda + k0 + ch * 8;
        cpasync16(sl + arr * AOFF_LO + row * APE + ch * 8, src);
    }
#pragma unroll
    for (int i = 0; i < NT / 2; i++) {
        int c = tid + i * 256;
        int row = c >> 3, ch = c & 7;
        cpasync16(sl + BOFF + row * APE + ch * 8, Bh + (size_t)(n0 + row) * K + k0 + ch * 8);
    }
}

// mode 0: plain store to out0[gm*ldc+n]
// mode 1: Wp (+bias, transpose to [b][t][n], n<DICT)
// mode 2: LSTM1 cell update   mode 3: LSTM2 cell update
// mode 4: plain store + d_bias1p[n]  (base1p)
template <int NT, int NSTG>
__device__ __forceinline__ void gemm_core(
    __half* dyn, int K, int mode,
    const __half* Ahi, const __half* Alo, const __half* Bh, int lda,
    const float* bias, float* out0, int ldc, int gm0, int n0, int t) {
    constexpr int NTL = 16 * NT;
    constexpr int SLOT = 9216 + NTL * APE;
    const int tid = threadIdx.x;
    const int lane = tid & 31, w = tid >> 5;
    const int mw = w & 3, nw = w >> 2;
    const int nst = K / KC;

#pragma unroll
    for (int p = 0; p < NSTG - 1; p++) {
        if (p < nst)
            stage_copy<NT>(dyn + p * SLOT, tid, Ahi, Alo, Bh, lda, K, gm0, n0, p * KC);
        CP_COMMIT();
    }

    const int ar = mw * 16 + (lane & 15);
    const int ac = (lane >> 4) * 8;
    const int t16 = lane & 15;
    const int bc = (t16 >> 3) * 8;

    float c[NT][2][4];
#pragma unroll
    for (int a = 0; a < NT; a++)
#pragma unroll
        for (int b = 0; b < 2; b++)
#pragma unroll
            for (int i = 0; i < 4; i++) c[a][b][i] = 0.f;

    int rd = 0;
    for (int s = 0; s < nst; s++) {
        asm volatile("cp.async.wait_group %0;" :: "n"(NSTG - 2) : "memory");
        __syncthreads();
        int wrslot = rd - 1;
        if (wrslot < 0) wrslot += NSTG;
        if (s + NSTG - 1 < nst)
            stage_copy<NT>(dyn + wrslot * SLOT, tid, Ahi, Alo, Bh, lda, K, gm0, n0,
                           (s + NSTG - 1) * KC);
        CP_COMMIT();

        const __half* sl = dyn + rd * SLOT;
#pragma unroll
        for (int kh = 0; kh < 4; kh++) {
            uint32_t ah[4], al[4];
            ldsm_x4(ah, sl + ar * APE + kh * 16 + ac);
            ldsm_x4(al, sl + AOFF_LO + ar * APE + kh * 16 + ac);
#pragma unroll
            for (int nt = 0; nt < NT; nt++) {
                uint32_t bh[2];
                ldsm_x2(bh, sl + BOFF + (nw * (NT * 8) + nt * 8 + (t16 & 7)) * APE +
                                kh * 16 + bc);
                mma16816(c[nt][0], ah, bh);
                mma16816(c[nt][1], al, bh);
            }
        }
        rd++;
        if (rd == NSTG) rd = 0;
    }
    asm volatile("cp.async.wait_group 0;" ::: "memory");
    __syncthreads();

    float c0[NT][4];
#pragma unroll
    for (int nt = 0; nt < NT; nt++)
#pragma unroll
        for (int i = 0; i < 4; i++) c0[nt][i] = c[nt][0][i] + c[nt][1][i];

    if (mode <= 1 || mode == 4) {
#pragma unroll
        for (int nt = 0; nt < NT; nt++) {
#pragma unroll
            for (int i = 0; i < 4; i++) {
                int m = mw * 16 + (lane >> 2) + ((i >> 1) << 3);
                int nl = nw * (NT * 8) + nt * 8 + ((lane & 3) << 1) + (i & 1);
                int gm = gm0 + m, n = n0 + nl;
                float v = c0[nt][i];
                if (mode == 0) {
                    out0[(size_t)gm * ldc + n] = v;
                } else if (mode == 4) {
                    out0[(size_t)gm * ldc + n] = v + d_bias1p[n];
                } else if (n < DICT) {
                    int tt = gm >> 6, b = gm & 63;
                    out0[((size_t)b * NSTEP + tt) * DICT + n] = v + bias[n];
                }
            }
        }
    } else {
        float* Gs = (float*)dyn;  // [64][NTL+4]
        const float* add1 = (mode == 2) ? d_base1p : d_bias2p;
        const float* add2 = d_wc + (size_t)t * Bsz * G4P;
        float* cbuf = (mode == 2) ? d_c1 : d_c2;
#pragma unroll
        for (int nt = 0; nt < NT; nt++) {
#pragma unroll
            for (int i = 0; i < 4; i++) {
                int m = mw * 16 + (lane >> 2) + ((i >> 1) << 3);
                int nl = nw * (NT * 8) + nt * 8 + ((lane & 3) << 1) + (i & 1);
                int n = n0 + nl;
                float addv = (mode == 2)
                                 ? (add1[(size_t)m * G4P + n] + add2[(size_t)m * G4P + n])
                                 : add1[n];
                Gs[m * (NTL + 4) + nl] = c0[nt][i] + addv;
            }
        }
        __syncthreads();
        for (int p = tid; p < Bsz * (NTL / 4); p += 256) {
            int b = p / (NTL / 4), jl = p % (NTL / 4);
            int j = (n0 >> 2) + jl;
            if (j < DL) {
                float ig = Gs[b * (NTL + 4) + jl * 4 + 0];
                float fg = Gs[b * (NTL + 4) + jl * 4 + 1];
                float gg = Gs[b * (NTL + 4) + jl * 4 + 2];
                float og = Gs[b * (NTL + 4) + jl * 4 + 3];
                float cn = sigf(fg) * cbuf[b * DL + j] + sigf(ig) * tanhf(gg);
                float h = sigf(og) * tanhf(cn);
                cbuf[b * DL + j] = cn;
                __half hh, hl;
                split1(h, hh, hl);
                if (mode == 2) {
                    d_x2hi[(size_t)b * K2P + j] = hh;
                    d_x2lo[(size_t)b * K2P + j] = hl;
                    d_x2hi[(size_t)b * K2P + 3048 + j] = d_x1hi[(size_t)b * K1P + j];
                    d_x2lo[(size_t)b * K2P + 3048 + j] = d_x1lo[(size_t)b * K1P + j];
                } else {
                    d_x1hi[(size_t)b * K1P + j] = hh;
                    d_x1lo[(size_t)b * K1P + j] = hl;
                    d_x1hi[(size_t)b * K1P + DL + j] = d_x2hi[(size_t)b * K2P + j];
                    d_x1lo[(size_t)b * K1P + DL + j] = d_x2lo[(size_t)b * K2P + j];
                    size_t ho = ((size_t)t * Bsz + b) * KEP + j;
                    d_h2hi[ho] = hh;
                    d_h2lo[ho] = hl;
                }
            }
        }
    }
}

// ---------------- loop GEMM kernel (narrow, NT=2/NSTG=4) ----------------
// mode 2: LSTM1 (asel x1, wsel W1)   mode 3: LSTM2 (asel x2, wsel W2)
__global__ void __launch_bounds__(256) mma_k(int K, int mode, int lda, int t) {
    extern __shared__ __align__(16) __half dyn[];
    const __half *Ahi, *Alo, *Bh;
    if (mode == 2) { Ahi = d_x1hi; Alo = d_x1lo; Bh = d_W1hi; }
    else           { Ahi = d_x2hi; Alo = d_x2lo; Bh = d_W2hi; }
    gemm_core<2, 4>(dyn, K, mode, Ahi, Alo, Bh, lda, (const float*)0, (float*)0, 0,
                    0, blockIdx.x * 32, t);
}

// wc + img_emb + base1p fused (wide, NT=4/NSTG=3, 2 CTAs/SM)
__global__ void __launch_bounds__(256) mma_dual() {
    extern __shared__ __align__(16) __half dyn[];
    int by = blockIdx.y, bx = blockIdx.x;
    if (by < NSTEP) {
        gemm_core<4, 3>(dyn, KEP, 0, d_embhi, d_emblo, d_Wehi, KEP,
                        (const float*)0, d_wc, G4P, by * 64, bx * 64, 0);
    } else if (by < NSTEP + (NF * Bsz) / 64) {
        if (bx >= DATT / 64) return;
        gemm_core<4, 3>(dyn, DIMG, 0, d_feathi, d_featlo, d_Waihi, DIMG,
                        (const float*)0, d_imgemb, DATT, (by - NSTEP) * 64, bx * 64, 0);
    } else {
        gemm_core<4, 3>(dyn, DIMG, 4, d_vmhi, d_vmlo, d_W1vhi, DIMG,
                        (const float*)0, d_base1p, G4P, 0, bx * 64, 0);
    }
}

__global__ void __launch_bounds__(256) mma_wp(const float* __restrict__ bias,
                                              float* __restrict__ out) {
    extern __shared__ __align__(16) __half dyn[];
    gemm_core<4, 3>(dyn, KEP, 1, d_h2hi, d_h2lo, d_Wphi, KEP,
                    bias, out, 0, blockIdx.y * 64, blockIdx.x * 64, 0);
}

// ---------------- fused precompute ----------------
// segments (4-elem chunk ids unless noted):
//   [0,  C0)   W1 gates   4096*512
//   [C0, C1)   W2 gates   4096*1024
//   [C1, C2)   We gates   4096*256
//   [C2, C3)   Wp         9984*256
//   [C3, C4)   Wa_img     512*512
//   [C4, C4V)  W1v gates  4096*512
//   [C4V,C5)   feats hi/lo 2304*512
//   [C5, C6)   vmean (+hi/lo) elem ids 64*2048
//   [C6, C7)   bias2p elem ids 4096
//   [C7, CT)   bias1p elem ids 4096
#define C0  2097152
#define C1  6291456
#define C2  7340032
#define C3  9895936
#define C4  10158080
#define C4V 12255232
#define C5  13434880
#define C6  13565952
#define C7  13570048
#define CT  13574144
__global__ void k_prep(const float* __restrict__ W1_ih, const float* __restrict__ W1_hh,
                       const float* __restrict__ W2_ih, const float* __restrict__ W2_hh,
                       const float* __restrict__ Wp, const float* __restrict__ Wa_img,
                       const float* __restrict__ feats,
                       const float* __restrict__ b1_ih, const float* __restrict__ b1_hh,
                       const float* __restrict__ b2_ih, const float* __restrict__ b2_hh) {
    int gi = blockIdx.x * 256 + threadIdx.x;
    if (gi >= CT) return;
    if (gi < C4V) {
        const float* Wih;
        const float* Whh = (const float*)0;
        int ihld = 0, splitcol = 0, Kreal, KP, Nvalid = 0;
        __half* dsthi;
        int c, n, k;
        int kind;  // 0 gates, 1 plain, 2 w1v
        if (gi < C0) {
            c = gi; n = c >> 9; k = (c & 511) << 2;
            Wih = W1_ih; Whh = W1_hh; ihld = 4048; splitcol = 1000; Kreal = 2000; KP = 2048;
            dsthi = d_W1hi; kind = 0;
        } else if (gi < C1) {
            c = gi - C0; n = c >> 10; k = (c & 1023) << 2;
            Wih = W2_ih; Whh = W2_hh; ihld = 3048; splitcol = 3048; Kreal = 4048; KP = 4096;
            dsthi = d_W2hi; kind = 0;
        } else if (gi < C2) {
            c = gi - C1; n = c >> 8; k = (c & 255) << 2;
            Wih = W1_ih + 3048; Whh = W1_hh; ihld = 4048; splitcol = 1024; Kreal = 1000;
            KP = 1024; dsthi = d_Wehi; kind = 0;
        } else if (gi < C3) {
            c = gi - C2; n = c >> 8; k = (c & 255) << 2;
            Wih = Wp; Kreal = 1000; KP = 1024; dsthi = d_Wphi; kind = 1;
            ihld = 1000; Nvalid = DICT;
        } else if (gi < C4) {
            c = gi - C3; n = c >> 9; k = (c & 511) << 2;
            Wih = Wa_img; Kreal = 2048; KP = 2048; dsthi = d_Waihi; kind = 1;
            ihld = 2048; Nvalid = DATT;
        } else {                  // W1v: permuted W1_ih[:,1000:3048]
            c = gi - C4; n = c >> 9; k = (c & 511) << 2;
            Wih = W1_ih; Kreal = 2048; KP = 2048; dsthi = d_W1vhi; kind = 2;
            ihld = 4048;
        }
        float4 v = make_float4(0.f, 0.f, 0.f, 0.f);
        if (kind == 0) {
            int j = n >> 2, g = n & 3;
            if (j < DL && k < Kreal) {
                int r = g * DL + j;
                v = (k < splitcol) ? *(const float4*)&Wih[(size_t)r * ihld + k]
                                   : *(const float4*)&Whh[(size_t)r * DL + (k - splitcol)];
            }
        } else if (kind == 1) {
            if (n < Nvalid && k < Kreal)
                v = *(const float4*)&Wih[(size_t)n * ihld + k];
        } else {
            int j = n >> 2, g = n & 3;
            if (j < DL) {
                int r = g * DL + j;
                v = *(const float4*)&Wih[(size_t)r * ihld + 1000 + k];
            }
        }
        __half2 h0 = __floats2half2_rn(v.x, v.y);
        __half2 h1 = __floats2half2_rn(v.z, v.w);
        *(uint2*)&dsthi[(size_t)n * KP + k] = make_uint2(*(uint32_t*)&h0, *(uint32_t*)&h1);
    } else if (gi < C5) {
        int c = gi - C4V;
        int idx = c << 2;
        float4 v = *(const float4*)&feats[idx];
        __half h0, l0, h1, l1, h2, l2, h3, l3;
        split1(v.x, h0, l0); split1(v.y, h1, l1); split1(v.z, h2, l2); split1(v.w, h3, l3);
        __half2 hh0(h0, h1), hh1(h2, h3), ll0(l0, l1), ll1(l2, l3);
        *(uint2*)&d_feathi[idx] = make_uint2(*(uint32_t*)&hh0, *(uint32_t*)&hh1);
        *(uint2*)&d_featlo[idx] = make_uint2(*(uint32_t*)&ll0, *(uint32_t*)&ll1);
    } else if (gi < C6) {
        int i = gi - C5;
        int b = i / DIMG, f = i % DIMG;
        const float* p = feats + (size_t)b * NF * DIMG + f;
        float s = 0.f;
#pragma unroll
        for (int n = 0; n < NF; n++) s += p[n * DIMG];
        s *= (1.0f / NF);
        __half hi, lo;
        split1(s, hi, lo);
        d_vmhi[i] = hi; d_vmlo[i] = lo;
    } else if (gi < C7) {
        int n = gi - C6;
        int j = n >> 2, g = n & 3;
        d_bias2p[n] = (j < DL) ? (b2_ih[g * DL + j] + b2_hh[g * DL + j]) : 0.f;
    } else {
        int n = gi - C7;
        int j = n >> 2, g = n & 3;
        d_bias1p[n] = (j < DL) ? (b1_ih[g * DL + j] + b1_hh[g * DL + j]) : 0.f;
    }
}

// ---------------- fused state init + word embeddings ----------------
#define MTOT (Bsz * K2P + NSTEP * Bsz * KEP)
__global__ void k_misc(const float* __restrict__ h1_0, const float* __restrict__ c1_0,
                       const float* __restrict__ h2_0, const float* __restrict__ c2_0,
                       const float* __restrict__ W_embed,
                       const int* __restrict__ true_words) {
    int i0 = blockIdx.x * 256 + threadIdx.x;
    if (i0 >= MTOT) return;
    if (i0 < Bsz * K2P) {
        int i = i0;
        int b = i >> 12, j = i & 4095;
        __half hi, lo;
        if (j < DL) {
            split1(h1_0[j], hi, lo);
            d_x2hi[i] = hi; d_x2lo[i] = lo;
        } else if (j >= 3048 && j < 3048 + DL) {
            split1(h2_0[j - 3048], hi, lo);
            d_x2hi[i] = hi; d_x2lo[i] = lo;
        } else if (j >= 4048) {
            d_x2hi[i] = __float2half(0.f); d_x2lo[i] = __float2half(0.f);
        }
        if (j < K1P) {
            float v = 0.f;
            if (j < DL) v = h2_0[j];
            else if (j < 2 * DL) v = h1_0[j - DL];
            split1(v, hi, lo);
            d_x1hi[b * K1P + j] = hi; d_x1lo[b * K1P + j] = lo;
        }
        if (j < DL) {
            d_c1[b * DL + j] = c1_0[j];
            d_c2[b * DL + j] = c2_0[j];
        }
    } else {
        int i = i0 - Bsz * K2P;
        int tb = i >> 10, e = i & 1023;
        float v = 0.f;
        if (e < DL) {
            int t = tb / Bsz, b = tb % Bsz;
            int idx = (t == 0) ? 1 : true_words[b * 20 + t];
            v = W_embed[(size_t)e * DICT + idx];
        }
        __half hi, lo;
        split1(v, hi, lo);
        d_embhi[i] = hi; d_emblo[i] = lo;
    }
}

// ---------------- attention projection: proj[b,a] = h1[b,:] . Wa_h[a,:] ----------------
__global__ void __launch_bounds__(256) attn_proj(const float* __restrict__ Wa_h) {
    __shared__ float Ws[8][64];
    __shared__ float Hs[64][65];
    int a0 = blockIdx.x * 8;
    int tid = threadIdx.x;
    float acc0 = 0.f, acc1 = 0.f;
    for (int k0 = 0; k0 < DL; k0 += 64) {
        for (int i = tid; i < 8 * 64; i += 256) {
            int a = i >> 6, kk = i & 63;
            int gk = k0 + kk;
            Ws[a][kk] = (gk < DL) ? Wa_h[(size_t)(a0 + a) * DL + gk] : 0.f;
        }
        for (int i = tid; i < 64 * 64; i += 256) {
            int bb = i >> 6, kk = i & 63;
            int gk = k0 + kk;
            float hv = 0.f;
            if (gk < DL)
                hv = __half2float(d_x2hi[(size_t)bb * K2P + gk]) +
                     __half2float(d_x2lo[(size_t)bb * K2P + gk]);
            Hs[bb][kk] = hv;
        }
        __syncthreads();
        {
            int a = tid >> 6, bb = tid & 63;
            float s = 0.f;
#pragma unroll
            for (int kk = 0; kk < 64; kk++) s += Ws[a][kk] * Hs[bb][kk];
            acc0 += s;
        }
        {
            int o = tid + 256;
            int a = o >> 6, bb = o & 63;
            float s = 0.f;
#pragma unroll
            for (int kk = 0; kk < 64; kk++) s += Ws[a][kk] * Hs[bb][kk];
            acc1 += s;
        }
        __syncthreads();
    }
    {
        int a = tid >> 6, bb = tid & 63;
        d_proj[bb * DATT + a0 + a] = acc0;
    }
    {
        int o = tid + 256;
        int a = o >> 6, bb = o & 63;
        d_proj[bb * DATT + a0 + a] = acc1;
    }
}

// ---------------- attention: logits -> softmax -> v_hat (split into x2) ----------------
__global__ void __launch_bounds__(256) attn_kernel(const float* __restrict__ feats,
                                                   const float* __restrict__ wa,
                                                   const float* __restrict__ ba) {
    __shared__ float proj_s[DATT];
    __shared__ float ls[NF];
    int b = blockIdx.x;
    int tid = threadIdx.x;
    int w = tid >> 5, lane = tid & 31;

    proj_s[tid] = d_proj[b * DATT + tid];
    proj_s[tid + 256] = d_proj[b * DATT + tid + 256];
    __syncthreads();

    for (int n = w; n < NF; n += 8) {
        const float* ie = d_imgemb + ((size_t)b * NF + n) * DATT;
        float s = 0.f;
        for (int a = lane; a < DATT; a += 32)
            s += tanhf(ie[a] + proj_s[a]) * wa[a];
#pragma unroll
        for (int off = 16; off; off >>= 1) s += __shfl_down_sync(0xffffffffu, s, off);
        if (lane == 0) ls[n] = s + ba[0];
    }
    __syncthreads();
    if (tid == 0) {
        float mx = -1e30f;
        for (int n = 0; n < NF; n++) mx = fmaxf(mx, ls[n]);
        float sum = 0.f;
        for (int n = 0; n < NF; n++) {
            float e = expf(ls[n] - mx);
            ls[n] = e;
            sum += e;
        }
        float inv = 1.f / sum;
        for (int n = 0; n < NF; n++) ls[n] *= inv;
    }
    __syncthreads();
    const float* fb = feats + (size_t)b * NF * DIMG;
    for (int f = tid; f < DIMG; f += 256) {
        float s = 0.f;
#pragma unroll
        for (int n = 0; n < NF; n++) s += ls[n] * fb[(size_t)n * DIMG + f];
        __half hh, hl;
        split1(s, hh, hl);
        d_x2hi[(size_t)b * K2P + DL + f] = hh;
        d_x2lo[(size_t)b * K2P + DL + f] = hl;
    }
}

// ---------------- launch ----------------
extern "C" void kernel_launch(void* const* d_in, const int* in_sizes, int n_in,
                              void* d_out, int out_size) {
    const float* image_feats = (const float*)d_in[0];
    const int* true_words = (const int*)d_in[2];
    const float* W_embed = (const float*)d_in[3];
    const float* W1_ih = (const float*)d_in[4];
    const float* W1_hh = (const float*)d_in[5];
    const float* b1_ih = (const float*)d_in[6];
    const float* b1_hh = (const float*)d_in[7];
    const float* W2_ih = (const float*)d_in[8];
    const float* W2_hh = (const float*)d_in[9];
    const float* b2_ih = (const float*)d_in[10];
    const float* b2_hh = (const float*)d_in[11];
    const float* Wa_img = (const float*)d_in[12];
    const float* Wa_h = (const float*)d_in[13];
    const float* wa = (const float*)d_in[14];
    const float* ba = (const float*)d_in[15];
    const float* Wp = (const float*)d_in[16];
    const float* bp = (const float*)d_in[17];
    const float* h1_0 = (const float*)d_in[18];
    const float* c1_0 = (const float*)d_in[19];
    const float* h2_0 = (const float*)d_in[20];
    const float* c2_0 = (const float*)d_in[21];

    cudaFuncSetAttribute(mma_k, cudaFuncAttributeMaxDynamicSharedMemorySize, SMEM_L);
    cudaFuncSetAttribute(mma_dual, cudaFuncAttributeMaxDynamicSharedMemorySize, SMEM_W4);
    cudaFuncSetAttribute(mma_wp, cudaFuncAttributeMaxDynamicSharedMemorySize, SMEM_W4);

    // launch 0: fused precompute (all splits + vmean + biases)
    k_prep<<<(CT + 255) / 256, 256>>>(W1_ih, W1_hh, W2_ih, W2_hh, Wp, Wa_img,
                                      image_feats, b1_ih, b1_hh, b2_ih, b2_hh);
    // launch 1: state init + word embeddings
    k_misc<<<(MTOT + 255) / 256, 256>>>(h1_0, c1_0, h2_0, c2_0, W_embed, true_words);
    // launch 2: wc + img_emb + base1p fused (NT=4, 2 CTAs/SM)
    mma_dual<<<dim3(G4P / 64, NSTEP + (NF * Bsz) / 64 + 1), 256, SMEM_W4>>>();

    // ---- recurrent loop  (launch 3 = first LSTM1 GEMM -> ncu -s 5 captures it) ----
    for (int t = 0; t < NSTEP; t++) {
        mma_k<<<dim3(G4P / 32, 1), 256, SMEM_L>>>(K1P, 2, K1P, t);
        attn_proj<<<DATT / 8, 256>>>(Wa_h);
        attn_kernel<<<Bsz, 256>>>(image_feats, wa, ba);
        mma_k<<<dim3(G4P / 32, 1), 256, SMEM_L>>>(K2P, 3, K2P, t);
    }

    // ---- final: out[b,t,:] = h2all[t,b,:] @ Wp^T + bp ----
    mma_wp<<<dim3(DICTP / 64, NSTEP), 256, SMEM_W4>>>(bp, (float*)d_out);
}

// round 16
// speedup vs baseline: 1.0141x; 1.0141x over previous
#include <cuda_runtime.h>
#include <cuda_fp16.h>
#include <math.h>
#include <stdint.h>

#define Bsz   64
#define DL    1000
#define DIMG  2048
#define NF    36
#define DATT  512
#define DICT  9956
#define DICTP 9984
#define NSTEP 19
#define G4P   4096
#define K1P   2048
#define K2P   4096
#define KEP   1024

#define KC    64
#define APE   72
#define AOFF_LO 4608            /* 64*APE halfs */
#define BOFF    9216            /* 2*4608 halfs */
#define SMEM_L  92160           /* 4 stages * (9216+ 32*72) halfs * 2B */
#define SMEM_W  110592          /* 3 stages * (9216+128*72) halfs * 2B */

// ---------------- device scratch (static; allocation-free) ----------------
__device__ __align__(16) __half d_W1hi[G4P * K1P];
__device__ __align__(16) __half d_W2hi[G4P * K2P];
__device__ __align__(16) __half d_Wehi[G4P * KEP];
__device__ __align__(16) __half d_Wphi[DICTP * KEP];
__device__ __align__(16) __half d_Waihi[DATT * DIMG];
__device__ __align__(16) __half d_W1vhi[G4P * DIMG];
__device__ __align__(16) __half d_feathi[NF * Bsz * DIMG];
__device__ __align__(16) __half d_featlo[NF * Bsz * DIMG];
__device__ __align__(16) __half d_embhi[NSTEP * Bsz * KEP];
__device__ __align__(16) __half d_emblo[NSTEP * Bsz * KEP];
__device__ __align__(16) __half d_h2hi[NSTEP * Bsz * KEP];
__device__ __align__(16) __half d_h2lo[NSTEP * Bsz * KEP];
__device__ __align__(16) __half d_x1hi[Bsz * K1P];
__device__ __align__(16) __half d_x1lo[Bsz * K1P];
__device__ __align__(16) __half d_x2hi[Bsz * K2P];
__device__ __align__(16) __half d_x2lo[Bsz * K2P];
__device__ __align__(16) __half d_vmhi[Bsz * DIMG];
__device__ __align__(16) __half d_vmlo[Bsz * DIMG];

__device__ __align__(16) float d_wc[NSTEP * Bsz * G4P];
__device__ __align__(16) float d_imgemb[Bsz * NF * DATT];
__device__ __align__(16) float d_base1p[Bsz * G4P];
__device__ __align__(16) float d_bias1p[G4P];
__device__ __align__(16) float d_bias2p[G4P];
__device__ __align__(16) float d_c1[Bsz * DL];
__device__ __align__(16) float d_c2[Bsz * DL];
__device__ __align__(16) float d_proj[Bsz * DATT];

__device__ __forceinline__ float sigf(float x) { return 1.f / (1.f + expf(-x)); }
__device__ __forceinline__ void split1(float v, __half& hi, __half& lo) {
    hi = __float2half(v);
    lo = __float2half(v - __half2float(hi));
}

__device__ __forceinline__ void ldsm_x4(uint32_t* r, const void* p) {
    uint32_t addr = (uint32_t)__cvta_generic_to_shared(p);
    asm volatile("ldmatrix.sync.aligned.m8n8.x4.shared.b16 {%0,%1,%2,%3}, [%4];"
                 : "=r"(r[0]), "=r"(r[1]), "=r"(r[2]), "=r"(r[3]) : "r"(addr));
}
__device__ __forceinline__ void ldsm_x2(uint32_t* r, const void* p) {
    uint32_t addr = (uint32_t)__cvta_generic_to_shared(p);
    asm volatile("ldmatrix.sync.aligned.m8n8.x2.shared.b16 {%0,%1}, [%2];"
                 : "=r"(r[0]), "=r"(r[1]) : "r"(addr));
}
__device__ __forceinline__ void mma16816(float* c, const uint32_t* a, const uint32_t* b) {
    asm volatile("mma.sync.aligned.m16n8k16.row.col.f32.f16.f16.f32 "
                 "{%0,%1,%2,%3}, {%4,%5,%6,%7}, {%8,%9}, {%0,%1,%2,%3};"
                 : "+f"(c[0]), "+f"(c[1]), "+f"(c[2]), "+f"(c[3])
                 : "r"(a[0]), "r"(a[1]), "r"(a[2]), "r"(a[3]), "r"(b[0]), "r"(b[1]));
}
__device__ __forceinline__ void cpasync16(__half* dst, const __half* src) {
    uint32_t d = (uint32_t)__cvta_generic_to_shared(dst);
    asm volatile("cp.async.cg.shared.global [%0], [%1], 16;" :: "r"(d), "l"(src));
}
#define CP_COMMIT() asm volatile("cp.async.commit_group;" ::: "memory")

// ---------------- wide GEMM core (256 threads, NT n-tiles per warp-col) ----------------
template <int NT>
__device__ __forceinline__ void stage_copy(__half* sl, int tid,
                                           const __half* Ahi, const __half* Alo,
                                           const __half* Bh, int lda, int K,
                                           int gm0, int n0, int k0) {
#pragma unroll
    for (int i = 0; i < 4; i++) {
        int c = tid + i * 256;
        int arr = c >> 9, rem = c & 511;
        int row = rem >> 3, ch = rem & 7;
        const __half* src = (arr ? Alo : Ahi) + (size_t)(gm0 + row) * lda + k0 + ch * 8;
        cpasync16(sl + arr * AOFF_LO + row * APE + ch * 8, src);
    }
#pragma unroll
    for (int i = 0; i < NT / 2; i++) {
        int c = tid + i * 256;
        int row = c >> 3, ch = c & 7;
        cpasync16(sl + BOFF + row * APE + ch * 8, Bh + (size_t)(n0 + row) * K + k0 + ch * 8);
    }
}

// mode 0: plain store   mode 1: Wp (+bias, transpose, n<DICT)   mode 4: +bias1p
template <int NT, int NSTG>
__device__ __forceinline__ void gemm_core(
    __half* dyn, int K, int mode,
    const __half* Ahi, const __half* Alo, const __half* Bh, int lda,
    const float* bias, float* out0, int ldc, int gm0, int n0) {
    constexpr int NTL = 16 * NT;
    constexpr int SLOT = 9216 + NTL * APE;
    const int tid = threadIdx.x;
    const int lane = tid & 31, w = tid >> 5;
    const int mw = w & 3, nw = w >> 2;
    const int nst = K / KC;

#pragma unroll
    for (int p = 0; p < NSTG - 1; p++) {
        if (p < nst)
            stage_copy<NT>(dyn + p * SLOT, tid, Ahi, Alo, Bh, lda, K, gm0, n0, p * KC);
        CP_COMMIT();
    }

    const int ar = mw * 16 + (lane & 15);
    const int ac = (lane >> 4) * 8;
    const int t16 = lane & 15;
    const int bc = (t16 >> 3) * 8;

    float c[NT][2][4];
#pragma unroll
    for (int a = 0; a < NT; a++)
#pragma unroll
        for (int b = 0; b < 2; b++)
#pragma unroll
            for (int i = 0; i < 4; i++) c[a][b][i] = 0.f;

    int rd = 0;
    for (int s = 0; s < nst; s++) {
        asm volatile("cp.async.wait_group %0;" :: "n"(NSTG - 2) : "memory");
        __syncthreads();
        int wrslot = rd - 1;
        if (wrslot < 0) wrslot += NSTG;
        if (s + NSTG - 1 < nst)
            stage_copy<NT>(dyn + wrslot * SLOT, tid, Ahi, Alo, Bh, lda, K, gm0, n0,
                           (s + NSTG - 1) * KC);
        CP_COMMIT();

        const __half* sl = dyn + rd * SLOT;
#pragma unroll
        for (int kh = 0; kh < 4; kh++) {
            uint32_t ah[4], al[4];
            ldsm_x4(ah, sl + ar * APE + kh * 16 + ac);
            ldsm_x4(al, sl + AOFF_LO + ar * APE + kh * 16 + ac);
#pragma unroll
            for (int nt = 0; nt < NT; nt++) {
                uint32_t bh[2];
                ldsm_x2(bh, sl + BOFF + (nw * (NT * 8) + nt * 8 + (t16 & 7)) * APE +
                                kh * 16 + bc);
                mma16816(c[nt][0], ah, bh);
                mma16816(c[nt][1], al, bh);
            }
        }
        rd++;
        if (rd == NSTG) rd = 0;
    }
    asm volatile("cp.async.wait_group 0;" ::: "memory");
    __syncthreads();

#pragma unroll
    for (int nt = 0; nt < NT; nt++) {
#pragma unroll
        for (int i = 0; i < 4; i++) {
            int m = mw * 16 + (lane >> 2) + ((i >> 1) << 3);
            int nl = nw * (NT * 8) + nt * 8 + ((lane & 3) << 1) + (i & 1);
            int gm = gm0 + m, n = n0 + nl;
            float v = c[nt][0][i] + c[nt][1][i];
            if (mode == 0) {
                out0[(size_t)gm * ldc + n] = v;
            } else if (mode == 4) {
                out0[(size_t)gm * ldc + n] = v + d_bias1p[n];
            } else if (n < DICT) {
                int tt = gm >> 6, b = gm & 63;
                out0[((size_t)b * NSTEP + tt) * DICT + n] = v + bias[n];
            }
        }
    }
}

// ---------------- loop GEMM kernel: 512 threads, 16 warps, 64x32 tile ----------------
// mode 2: LSTM1 cell update   mode 3: LSTM2 cell update
__global__ void __launch_bounds__(512) mma_k(int K, int mode, int lda, int t) {
    extern __shared__ __align__(16) __half dyn[];
    constexpr int SLOT = 9216 + 32 * APE;  // 11520
    const __half *Ahi, *Alo, *Bh;
    if (mode == 2) { Ahi = d_x1hi; Alo = d_x1lo; Bh = d_W1hi; }
    else           { Ahi = d_x2hi; Alo = d_x2lo; Bh = d_W2hi; }

    const int tid = threadIdx.x;
    const int lane = tid & 31, w = tid >> 5;
    const int mw = w & 3, nw = w >> 2;   // 4 x 4 warp grid
    const int n0 = blockIdx.x * 32;
    const int nst = K / KC;

    // stage copy lambda-free macro body
    const int a_arr = tid >> 9;          // for i*512 pattern below
    (void)a_arr;
#define LSTAGE(k0_, slot_) do {                                                       \
    __half* _sl = dyn + (slot_) * SLOT;                                               \
    _Pragma("unroll")                                                                 \
    for (int _i = 0; _i < 2; _i++) {                                                  \
        int _c = tid + _i * 512;                                                      \
        int _arr = _c >> 9, _rem = _c & 511;                                          \
        int _row = _rem >> 3, _ch = _rem & 7;                                         \
        const __half* _src = (_arr ? Alo : Ahi) + (size_t)_row * lda + (k0_) + _ch * 8; \
        cpasync16(_sl + _arr * AOFF_LO + _row * APE + _ch * 8, _src);                 \
    }                                                                                 \
    if (tid < 256) {                                                                  \
        int _row = tid >> 3, _ch = tid & 7;                                           \
        cpasync16(_sl + BOFF + _row * APE + _ch * 8,                                  \
                  Bh + (size_t)(n0 + _row) * K + (k0_) + _ch * 8);                    \
    }                                                                                 \
} while (0)

#pragma unroll
    for (int p = 0; p < 3; p++) {
        if (p < nst) LSTAGE(p * KC, p);
        CP_COMMIT();
    }

    const int ar = mw * 16 + (lane & 15);
    const int ac = (lane >> 4) * 8;
    const int t16 = lane & 15;
    const int br = nw * 8 + (t16 & 7);
    const int bc = (t16 >> 3) * 8;

    float ch[4] = {0.f, 0.f, 0.f, 0.f};
    float cl[4] = {0.f, 0.f, 0.f, 0.f};

    int rd = 0;
    for (int s = 0; s < nst; s++) {
        asm volatile("cp.async.wait_group 2;" ::: "memory");
        __syncthreads();
        int wrslot = rd - 1;
        if (wrslot < 0) wrslot += 4;
        if (s + 3 < nst) LSTAGE((s + 3) * KC, wrslot);
        CP_COMMIT();

        const __half* sl = dyn + rd * SLOT;
#pragma unroll
        for (int kh = 0; kh < 4; kh++) {
            uint32_t ah[4], al[4], bh[2];
            ldsm_x4(ah, sl + ar * APE + kh * 16 + ac);
            ldsm_x4(al, sl + AOFF_LO + ar * APE + kh * 16 + ac);
            ldsm_x2(bh, sl + BOFF + br * APE + kh * 16 + bc);
            mma16816(ch, ah, bh);
            mma16816(cl, al, bh);
        }
        rd++;
        if (rd == 4) rd = 0;
    }
    asm volatile("cp.async.wait_group 0;" ::: "memory");
    __syncthreads();

    // ---- fused LSTM cell epilogue ----
    float* Gs = (float*)dyn;  // [64][36]
    const float* add1 = (mode == 2) ? d_base1p : d_bias2p;
    const float* add2 = d_wc + (size_t)t * Bsz * G4P;
    float* cbuf = (mode == 2) ? d_c1 : d_c2;
#pragma unroll
    for (int i = 0; i < 4; i++) {
        int m = mw * 16 + (lane >> 2) + ((i >> 1) << 3);
        int nl = nw * 8 + ((lane & 3) << 1) + (i & 1);
        int n = n0 + nl;
        float addv = (mode == 2)
                         ? (add1[(size_t)m * G4P + n] + add2[(size_t)m * G4P + n])
                         : add1[n];
        Gs[m * 36 + nl] = ch[i] + cl[i] + addv;
    }
    __syncthreads();
    {
        int p = tid;  // 512 = Bsz * 8
        int b = p >> 3, jl = p & 7;
        int j = (n0 >> 2) + jl;
        if (j < DL) {
            float ig = Gs[b * 36 + jl * 4 + 0];
            float fg = Gs[b * 36 + jl * 4 + 1];
            float gg = Gs[b * 36 + jl * 4 + 2];
            float og = Gs[b * 36 + jl * 4 + 3];
            float cn = sigf(fg) * cbuf[b * DL + j] + sigf(ig) * tanhf(gg);
            float h = sigf(og) * tanhf(cn);
            cbuf[b * DL + j] = cn;
            __half hh, hl;
            split1(h, hh, hl);
            if (mode == 2) {
                d_x2hi[(size_t)b * K2P + j] = hh;
                d_x2lo[(size_t)b * K2P + j] = hl;
                d_x2hi[(size_t)b * K2P + 3048 + j] = d_x1hi[(size_t)b * K1P + j];
                d_x2lo[(size_t)b * K2P + 3048 + j] = d_x1lo[(size_t)b * K1P + j];
            } else {
                d_x1hi[(size_t)b * K1P + j] = hh;
                d_x1lo[(size_t)b * K1P + j] = hl;
                d_x1hi[(size_t)b * K1P + DL + j] = d_x2hi[(size_t)b * K2P + j];
                d_x1lo[(size_t)b * K1P + DL + j] = d_x2lo[(size_t)b * K2P + j];
                size_t ho = ((size_t)t * Bsz + b) * KEP + j;
                d_h2hi[ho] = hh;
                d_h2lo[ho] = hl;
            }
        }
    }
#undef LSTAGE
}

// ---------------- wide batch GEMMs: wc + img_emb + base1p fused ----------------
__global__ void __launch_bounds__(256) mma_dual() {
    extern __shared__ __align__(16) __half dyn[];
    int by = blockIdx.y, bx = blockIdx.x;
    if (by < NSTEP) {
        gemm_core<8, 3>(dyn, KEP, 0, d_embhi, d_emblo, d_Wehi, KEP,
                        (const float*)0, d_wc, G4P, by * 64, bx * 128);
    } else if (by < NSTEP + (NF * Bsz) / 64) {
        if (bx >= DATT / 128) return;
        gemm_core<8, 3>(dyn, DIMG, 0, d_feathi, d_featlo, d_Waihi, DIMG,
                        (const float*)0, d_imgemb, DATT, (by - NSTEP) * 64, bx * 128);
    } else {
        gemm_core<8, 3>(dyn, DIMG, 4, d_vmhi, d_vmlo, d_W1vhi, DIMG,
                        (const float*)0, d_base1p, G4P, 0, bx * 128);
    }
}

__global__ void __launch_bounds__(256) mma_wp(const float* __restrict__ bias,
                                              float* __restrict__ out) {
    extern __shared__ __align__(16) __half dyn[];
    gemm_core<8, 3>(dyn, KEP, 1, d_h2hi, d_h2lo, d_Wphi, KEP,
                    bias, out, 0, blockIdx.y * 64, blockIdx.x * 128);
}

// ---------------- fused precompute ----------------
#define C0  2097152
#define C1  6291456
#define C2  7340032
#define C3  9895936
#define C4  10158080
#define C4V 12255232
#define C5  13434880
#define C6  13565952
#define C7  13570048
#define CT  13574144
__global__ void k_prep(const float* __restrict__ W1_ih, const float* __restrict__ W1_hh,
                       const float* __restrict__ W2_ih, const float* __restrict__ W2_hh,
                       const float* __restrict__ Wp, const float* __restrict__ Wa_img,
                       const float* __restrict__ feats,
                       const float* __restrict__ b1_ih, const float* __restrict__ b1_hh,
                       const float* __restrict__ b2_ih, const float* __restrict__ b2_hh) {
    int gi = blockIdx.x * 256 + threadIdx.x;
    if (gi >= CT) return;
    if (gi < C4V) {
        const float* Wih;
        const float* Whh = (const float*)0;
        int ihld = 0, splitcol = 0, Kreal, KP, Nvalid = 0;
        __half* dsthi;
        int c, n, k;
        int kind;  // 0 gates, 1 plain, 2 w1v
        if (gi < C0) {
            c = gi; n = c >> 9; k = (c & 511) << 2;
            Wih = W1_ih; Whh = W1_hh; ihld = 4048; splitcol = 1000; Kreal = 2000; KP = 2048;
            dsthi = d_W1hi; kind = 0;
        } else if (gi < C1) {
            c = gi - C0; n = c >> 10; k = (c & 1023) << 2;
            Wih = W2_ih; Whh = W2_hh; ihld = 3048; splitcol = 3048; Kreal = 4048; KP = 4096;
            dsthi = d_W2hi; kind = 0;
        } else if (gi < C2) {
            c = gi - C1; n = c >> 8; k = (c & 255) << 2;
            Wih = W1_ih + 3048; Whh = W1_hh; ihld = 4048; splitcol = 1024; Kreal = 1000;
            KP = 1024; dsthi = d_Wehi; kind = 0;
        } else if (gi < C3) {
            c = gi - C2; n = c >> 8; k = (c & 255) << 2;
            Wih = Wp; Kreal = 1000; KP = 1024; dsthi = d_Wphi; kind = 1;
            ihld = 1000; Nvalid = DICT;
        } else if (gi < C4) {
            c = gi - C3; n = c >> 9; k = (c & 511) << 2;
            Wih = Wa_img; Kreal = 2048; KP = 2048; dsthi = d_Waihi; kind = 1;
            ihld = 2048; Nvalid = DATT;
        } else {
            c = gi - C4; n = c >> 9; k = (c & 511) << 2;
            Wih = W1_ih; Kreal = 2048; KP = 2048; dsthi = d_W1vhi; kind = 2;
            ihld = 4048;
        }
        float4 v = make_float4(0.f, 0.f, 0.f, 0.f);
        if (kind == 0) {
            int j = n >> 2, g = n & 3;
            if (j < DL && k < Kreal) {
                int r = g * DL + j;
                v = (k < splitcol) ? *(const float4*)&Wih[(size_t)r * ihld + k]
                                   : *(const float4*)&Whh[(size_t)r * DL + (k - splitcol)];
            }
        } else if (kind == 1) {
            if (n < Nvalid && k < Kreal)
                v = *(const float4*)&Wih[(size_t)n * ihld + k];
        } else {
            int j = n >> 2, g = n & 3;
            if (j < DL) {
                int r = g * DL + j;
                v = *(const float4*)&Wih[(size_t)r * ihld + 1000 + k];
            }
        }
        __half2 h0 = __floats2half2_rn(v.x, v.y);
        __half2 h1 = __floats2half2_rn(v.z, v.w);
        *(uint2*)&dsthi[(size_t)n * KP + k] = make_uint2(*(uint32_t*)&h0, *(uint32_t*)&h1);
    } else if (gi < C5) {
        int c = gi - C4V;
        int idx = c << 2;
        float4 v = *(const float4*)&feats[idx];
        __half h0, l0, h1, l1, h2, l2, h3, l3;
        split1(v.x, h0, l0); split1(v.y, h1, l1); split1(v.z, h2, l2); split1(v.w, h3, l3);
        __half2 hh0(h0, h1), hh1(h2, h3), ll0(l0, l1), ll1(l2, l3);
        *(uint2*)&d_feathi[idx] = make_uint2(*(uint32_t*)&hh0, *(uint32_t*)&hh1);
        *(uint2*)&d_featlo[idx] = make_uint2(*(uint32_t*)&ll0, *(uint32_t*)&ll1);
    } else if (gi < C6) {
        int i = gi - C5;
        int b = i / DIMG, f = i % DIMG;
        const float* p = feats + (size_t)b * NF * DIMG + f;
        float s = 0.f;
#pragma unroll
        for (int n = 0; n < NF; n++) s += p[n * DIMG];
        s *= (1.0f / NF);
        __half hi, lo;
        split1(s, hi, lo);
        d_vmhi[i] = hi; d_vmlo[i] = lo;
    } else if (gi < C7) {
        int n = gi - C6;
        int j = n >> 2, g = n & 3;
        d_bias2p[n] = (j < DL) ? (b2_ih[g * DL + j] + b2_hh[g * DL + j]) : 0.f;
    } else {
        int n = gi - C7;
        int j = n >> 2, g = n & 3;
        d_bias1p[n] = (j < DL) ? (b1_ih[g * DL + j] + b1_hh[g * DL + j]) : 0.f;
    }
}

// ---------------- fused state init + word embeddings ----------------
#define MTOT (Bsz * K2P + NSTEP * Bsz * KEP)
__global__ void k_misc(const float* __restrict__ h1_0, const float* __restrict__ c1_0,
                       const float* __restrict__ h2_0, const float* __restrict__ c2_0,
                       const float* __restrict__ W_embed,
                       const int* __restrict__ true_words) {
    int i0 = blockIdx.x * 256 + threadIdx.x;
    if (i0 >= MTOT) return;
    if (i0 < Bsz * K2P) {
        int i = i0;
        int b = i >> 12, j = i & 4095;
        __half hi, lo;
        if (j < DL) {
            split1(h1_0[j], hi, lo);
            d_x2hi[i] = hi; d_x2lo[i] = lo;
        } else if (j >= 3048 && j < 3048 + DL) {
            split1(h2_0[j - 3048], hi, lo);
            d_x2hi[i] = hi; d_x2lo[i] = lo;
        } else if (j >= 4048) {
            d_x2hi[i] = __float2half(0.f); d_x2lo[i] = __float2half(0.f);
        }
        if (j < K1P) {
            float v = 0.f;
            if (j < DL) v = h2_0[j];
            else if (j < 2 * DL) v = h1_0[j - DL];
            split1(v, hi, lo);
            d_x1hi[b * K1P + j] = hi; d_x1lo[b * K1P + j] = lo;
        }
        if (j < DL) {
            d_c1[b * DL + j] = c1_0[j];
            d_c2[b * DL + j] = c2_0[j];
        }
    } else {
        int i = i0 - Bsz * K2P;
        int tb = i >> 10, e = i & 1023;
        float v = 0.f;
        if (e < DL) {
            int t = tb / Bsz, b = tb % Bsz;
            int idx = (t == 0) ? 1 : true_words[b * 20 + t];
            v = W_embed[(size_t)e * DICT + idx];
        }
        __half hi, lo;
        split1(v, hi, lo);
        d_embhi[i] = hi; d_emblo[i] = lo;
    }
}

// ---------------- attention projection: proj[b,a] = h1[b,:] . Wa_h[a,:] ----------------
__global__ void __launch_bounds__(256) attn_proj(const float* __restrict__ Wa_h) {
    __shared__ float Ws[8][64];
    __shared__ float Hs[64][65];
    int a0 = blockIdx.x * 8;
    int tid = threadIdx.x;
    float acc0 = 0.f, acc1 = 0.f;
    for (int k0 = 0; k0 < DL; k0 += 64) {
        for (int i = tid; i < 8 * 64; i += 256) {
            int a = i >> 6, kk = i & 63;
            int gk = k0 + kk;
            Ws[a][kk] = (gk < DL) ? Wa_h[(size_t)(a0 + a) * DL + gk] : 0.f;
        }
        for (int i = tid; i < 64 * 64; i += 256) {
            int bb = i >> 6, kk = i & 63;
            int gk = k0 + kk;
            float hv = 0.f;
            if (gk < DL)
                hv = __half2float(d_x2hi[(size_t)bb * K2P + gk]) +
                     __half2float(d_x2lo[(size_t)bb * K2P + gk]);
            Hs[bb][kk] = hv;
        }
        __syncthreads();
        {
            int a = tid >> 6, bb = tid & 63;
            float s = 0.f;
#pragma unroll
            for (int kk = 0; kk < 64; kk++) s += Ws[a][kk] * Hs[bb][kk];
            acc0 += s;
        }
        {
            int o = tid + 256;
            int a = o >> 6, bb = o & 63;
            float s = 0.f;
#pragma unroll
            for (int kk = 0; kk < 64; kk++) s += Ws[a][kk] * Hs[bb][kk];
            acc1 += s;
        }
        __syncthreads();
    }
    {
        int a = tid >> 6, bb = tid & 63;
        d_proj[bb * DATT + a0 + a] = acc0;
    }
    {
        int o = tid + 256;
        int a = o >> 6, bb = o & 63;
        d_proj[bb * DATT + a0 + a] = acc1;
    }
}

// ---------------- attention: logits -> softmax -> v_hat (split into x2) ----------------
__global__ void __launch_bounds__(256) attn_kernel(const float* __restrict__ feats,
                                                   const float* __restrict__ wa,
                                                   const float* __restrict__ ba) {
    __shared__ float proj_s[DATT];
    __shared__ float ls[NF];
    int b = blockIdx.x;
    int tid = threadIdx.x;
    int w = tid >> 5, lane = tid & 31;

    proj_s[tid] = d_proj[b * DATT + tid];
    proj_s[tid + 256] = d_proj[b * DATT + tid + 256];
    __syncthreads();

    for (int n = w; n < NF; n += 8) {
        const float* ie = d_imgemb + ((size_t)b * NF + n) * DATT;
        float s = 0.f;
        for (int a = lane; a < DATT; a += 32)
            s += tanhf(ie[a] + proj_s[a]) * wa[a];
#pragma unroll
        for (int off = 16; off; off >>= 1) s += __shfl_down_sync(0xffffffffu, s, off);
        if (lane == 0) ls[n] = s + ba[0];
    }
    __syncthreads();
    if (tid == 0) {
        float mx = -1e30f;
        for (int n = 0; n < NF; n++) mx = fmaxf(mx, ls[n]);
        float sum = 0.f;
        for (int n = 0; n < NF; n++) {
            float e = expf(ls[n] - mx);
            ls[n] = e;
            sum += e;
        }
        float inv = 1.f / sum;
        for (int n = 0; n < NF; n++) ls[n] *= inv;
    }
    __syncthreads();
    const float* fb = feats + (size_t)b * NF * DIMG;
    for (int f = tid; f < DIMG; f += 256) {
        float s = 0.f;
#pragma unroll
        for (int n = 0; n < NF; n++) s += ls[n] * fb[(size_t)n * DIMG + f];
        __half hh, hl;
        split1(s, hh, hl);
        d_x2hi[(size_t)b * K2P + DL + f] = hh;
        d_x2lo[(size_t)b * K2P + DL + f] = hl;
    }
}

// ---------------- launch ----------------
extern "C" void kernel_launch(void* const* d_in, const int* in_sizes, int n_in,
                              void* d_out, int out_size) {
    const float* image_feats = (const float*)d_in[0];
    const int* true_words = (const int*)d_in[2];
    const float* W_embed = (const float*)d_in[3];
    const float* W1_ih = (const float*)d_in[4];
    const float* W1_hh = (const float*)d_in[5];
    const float* b1_ih = (const float*)d_in[6];
    const float* b1_hh = (const float*)d_in[7];
    const float* W2_ih = (const float*)d_in[8];
    const float* W2_hh = (const float*)d_in[9];
    const float* b2_ih = (const float*)d_in[10];
    const float* b2_hh = (const float*)d_in[11];
    const float* Wa_img = (const float*)d_in[12];
    const float* Wa_h = (const float*)d_in[13];
    const float* wa = (const float*)d_in[14];
    const float* ba = (const float*)d_in[15];
    const float* Wp = (const float*)d_in[16];
    const float* bp = (const float*)d_in[17];
    const float* h1_0 = (const float*)d_in[18];
    const float* c1_0 = (const float*)d_in[19];
    const float* h2_0 = (const float*)d_in[20];
    const float* c2_0 = (const float*)d_in[21];

    cudaFuncSetAttribute(mma_k, cudaFuncAttributeMaxDynamicSharedMemorySize, SMEM_L);
    cudaFuncSetAttribute(mma_dual, cudaFuncAttributeMaxDynamicSharedMemorySize, SMEM_W);
    cudaFuncSetAttribute(mma_wp, cudaFuncAttributeMaxDynamicSharedMemorySize, SMEM_W);

    // launch 0: fused precompute (all splits + vmean + biases)
    k_prep<<<(CT + 255) / 256, 256>>>(W1_ih, W1_hh, W2_ih, W2_hh, Wp, Wa_img,
                                      image_feats, b1_ih, b1_hh, b2_ih, b2_hh);
    // launch 1: state init + word embeddings
    k_misc<<<(MTOT + 255) / 256, 256>>>(h1_0, c1_0, h2_0, c2_0, W_embed, true_words);
    // launch 2: wc + img_emb + base1p fused (NT=8)
    mma_dual<<<dim3(G4P / 128, NSTEP + (NF * Bsz) / 64 + 1), 256, SMEM_W>>>();

    // ---- recurrent loop  (first LSTM1 GEMM early for ncu capture) ----
    for (int t = 0; t < NSTEP; t++) {
        mma_k<<<dim3(G4P / 32, 1), 512, SMEM_L>>>(K1P, 2, K1P, t);
        attn_proj<<<DATT / 8, 256>>>(Wa_h);
        attn_kernel<<<Bsz, 256>>>(image_feats, wa, ba);
        mma_k<<<dim3(G4P / 32, 1), 512, SMEM_L>>>(K2P, 3, K2P, t);
    }

    // ---- final: out[b,t,:] = h2all[t,b,:] @ Wp^T + bp ----
    mma_wp<<<dim3(DICTP / 128, NSTEP), 256, SMEM_W>>>(bp, (float*)d_out);
}

// round 17
// speedup vs baseline: 1.0987x; 1.0834x over previous
#include <cuda_runtime.h>
#include <cuda_fp16.h>
#include <math.h>
#include <stdint.h>

#define Bsz   64
#define DL    1000
#define DIMG  2048
#define NF    36
#define DATT  512
#define DICT  9956
#define DICTP 9984
#define NSTEP 19
#define G4P   4096
#define K1P   2048
#define K2P   4096
#define KEP   1024

#define KC    64
#define APE   72
#define AOFF_LO 4608            /* 64*APE halfs */
#define BOFF    9216            /* 2*4608 halfs */
#define LSLOT   11520           /* 9216 + 32*72 halfs */
#define LNSTG   6
#define SMEM_L  138240          /* 6 * 11520 * 2B */
#define SMEM_W  110592          /* 3 stages * (9216+128*72) halfs * 2B */

// ---------------- device scratch (static; allocation-free) ----------------
__device__ __align__(16) __half d_W1hi[G4P * K1P];
__device__ __align__(16) __half d_W2hi[G4P * K2P];
__device__ __align__(16) __half d_Wehi[G4P * KEP];
__device__ __align__(16) __half d_Wphi[DICTP * KEP];
__device__ __align__(16) __half d_Waihi[DATT * DIMG];
__device__ __align__(16) __half d_W1vhi[G4P * DIMG];
__device__ __align__(16) __half d_feathi[NF * Bsz * DIMG];
__device__ __align__(16) __half d_featlo[NF * Bsz * DIMG];
__device__ __align__(16) __half d_embhi[NSTEP * Bsz * KEP];
__device__ __align__(16) __half d_emblo[NSTEP * Bsz * KEP];
__device__ __align__(16) __half d_h2hi[NSTEP * Bsz * KEP];
__device__ __align__(16) __half d_h2lo[NSTEP * Bsz * KEP];
__device__ __align__(16) __half d_x1hi[Bsz * K1P];
__device__ __align__(16) __half d_x1lo[Bsz * K1P];
__device__ __align__(16) __half d_x2hi[Bsz * K2P];
__device__ __align__(16) __half d_x2lo[Bsz * K2P];
__device__ __align__(16) __half d_vmhi[Bsz * DIMG];
__device__ __align__(16) __half d_vmlo[Bsz * DIMG];

__device__ __align__(16) float d_wc[NSTEP * Bsz * G4P];
__device__ __align__(16) float d_imgemb[Bsz * NF * DATT];
__device__ __align__(16) float d_base1p[Bsz * G4P];
__device__ __align__(16) float d_bias1p[G4P];
__device__ __align__(16) float d_bias2p[G4P];
__device__ __align__(16) float d_c1[Bsz * DL];
__device__ __align__(16) float d_c2[Bsz * DL];
__device__ __align__(16) float d_proj[Bsz * DATT];
__device__ __align__(16) float d_attnp[Bsz * 64];

__device__ __forceinline__ float sigf(float x) { return 1.f / (1.f + expf(-x)); }
__device__ __forceinline__ void split1(float v, __half& hi, __half& lo) {
    hi = __float2half(v);
    lo = __float2half(v - __half2float(hi));
}

__device__ __forceinline__ void ldsm_x4(uint32_t* r, const void* p) {
    uint32_t addr = (uint32_t)__cvta_generic_to_shared(p);
    asm volatile("ldmatrix.sync.aligned.m8n8.x4.shared.b16 {%0,%1,%2,%3}, [%4];"
                 : "=r"(r[0]), "=r"(r[1]), "=r"(r[2]), "=r"(r[3]) : "r"(addr));
}
__device__ __forceinline__ void ldsm_x2(uint32_t* r, const void* p) {
    uint32_t addr = (uint32_t)__cvta_generic_to_shared(p);
    asm volatile("ldmatrix.sync.aligned.m8n8.x2.shared.b16 {%0,%1}, [%2];"
                 : "=r"(r[0]), "=r"(r[1]) : "r"(addr));
}
__device__ __forceinline__ void mma16816(float* c, const uint32_t* a, const uint32_t* b) {
    asm volatile("mma.sync.aligned.m16n8k16.row.col.f32.f16.f16.f32 "
                 "{%0,%1,%2,%3}, {%4,%5,%6,%7}, {%8,%9}, {%0,%1,%2,%3};"
                 : "+f"(c[0]), "+f"(c[1]), "+f"(c[2]), "+f"(c[3])
                 : "r"(a[0]), "r"(a[1]), "r"(a[2]), "r"(a[3]), "r"(b[0]), "r"(b[1]));
}
__device__ __forceinline__ void cpasync16(__half* dst, const __half* src) {
    uint32_t d = (uint32_t)__cvta_generic_to_shared(dst);
    asm volatile("cp.async.cg.shared.global [%0], [%1], 16;" :: "r"(d), "l"(src));
}
#define CP_COMMIT() asm volatile("cp.async.commit_group;" ::: "memory")

// ---------------- wide GEMM core (256 threads, NT n-tiles per warp-col) ----------------
template <int NT>
__device__ __forceinline__ void stage_copy(__half* sl, int tid,
                                           const __half* Ahi, const __half* Alo,
                                           const __half* Bh, int lda, int K,
                                           int gm0, int n0, int k0) {
#pragma unroll
    for (int i = 0; i < 4; i++) {
        int c = tid + i * 256;
        int arr = c >> 9, rem = c & 511;
        int row = rem >> 3, ch = rem & 7;
        const __half* src = (arr ? Alo : Ahi) + (size_t)(gm0 + row) * lda + k0 + ch * 8;
        cpasync16(sl + arr * AOFF_LO + row * APE + ch * 8, src);
    }
#pragma unroll
    for (int i = 0; i < NT / 2; i++) {
        int c = tid + i * 256;
        int row = c >> 3, ch = c & 7;
        cpasync16(sl + BOFF + row * APE + ch * 8, Bh + (size_t)(n0 + row) * K + k0 + ch * 8);
    }
}

// mode 0: plain store   mode 1: Wp (+bias, transpose, n<DICT)   mode 4: +bias1p
template <int NT, int NSTG>
__device__ __forceinline__ void gemm_core(
    __half* dyn, int K, int mode,
    const __half* Ahi, const __half* Alo, const __half* Bh, int lda,
    const float* bias, float* out0, int ldc, int gm0, int n0) {
    constexpr int NTL = 16 * NT;
    constexpr int SLOT = 9216 + NTL * APE;
    const int tid = threadIdx.x;
    const int lane = tid & 31, w = tid >> 5;
    const int mw = w & 3, nw = w >> 2;
    const int nst = K / KC;

#pragma unroll
    for (int p = 0; p < NSTG - 1; p++) {
        if (p < nst)
            stage_copy<NT>(dyn + p * SLOT, tid, Ahi, Alo, Bh, lda, K, gm0, n0, p * KC);
        CP_COMMIT();
    }

    const int ar = mw * 16 + (lane & 15);
    const int ac = (lane >> 4) * 8;
    const int t16 = lane & 15;
    const int bc = (t16 >> 3) * 8;

    float c[NT][2][4];
#pragma unroll
    for (int a = 0; a < NT; a++)
#pragma unroll
        for (int b = 0; b < 2; b++)
#pragma unroll
            for (int i = 0; i < 4; i++) c[a][b][i] = 0.f;

    int rd = 0;
    for (int s = 0; s < nst; s++) {
        asm volatile("cp.async.wait_group %0;" :: "n"(NSTG - 2) : "memory");
        __syncthreads();
        int wrslot = rd - 1;
        if (wrslot < 0) wrslot += NSTG;
        if (s + NSTG - 1 < nst)
            stage_copy<NT>(dyn + wrslot * SLOT, tid, Ahi, Alo, Bh, lda, K, gm0, n0,
                           (s + NSTG - 1) * KC);
        CP_COMMIT();

        const __half* sl = dyn + rd * SLOT;
#pragma unroll
        for (int kh = 0; kh < 4; kh++) {
            uint32_t ah[4], al[4];
            ldsm_x4(ah, sl + ar * APE + kh * 16 + ac);
            ldsm_x4(al, sl + AOFF_LO + ar * APE + kh * 16 + ac);
#pragma unroll
            for (int nt = 0; nt < NT; nt++) {
                uint32_t bh[2];
                ldsm_x2(bh, sl + BOFF + (nw * (NT * 8) + nt * 8 + (t16 & 7)) * APE +
                                kh * 16 + bc);
                mma16816(c[nt][0], ah, bh);
                mma16816(c[nt][1], al, bh);
            }
        }
        rd++;
        if (rd == NSTG) rd = 0;
    }
    asm volatile("cp.async.wait_group 0;" ::: "memory");
    __syncthreads();

#pragma unroll
    for (int nt = 0; nt < NT; nt++) {
#pragma unroll
        for (int i = 0; i < 4; i++) {
            int m = mw * 16 + (lane >> 2) + ((i >> 1) << 3);
            int nl = nw * (NT * 8) + nt * 8 + ((lane & 3) << 1) + (i & 1);
            int gm = gm0 + m, n = n0 + nl;
            float v = c[nt][0][i] + c[nt][1][i];
            if (mode == 0) {
                out0[(size_t)gm * ldc + n] = v;
            } else if (mode == 4) {
                out0[(size_t)gm * ldc + n] = v + d_bias1p[n];
            } else if (n < DICT) {
                int tt = gm >> 6, b = gm & 63;
                out0[((size_t)b * NSTEP + tt) * DICT + n] = v + bias[n];
            }
        }
    }
}

// ---------------- loop GEMM kernel: 512 threads, 6-deep ring, 64x32 tile ----------------
// mode 2: LSTM1 cell update   mode 3: LSTM2 cell update
__global__ void __launch_bounds__(512) mma_k(int K, int mode, int lda, int t) {
    extern __shared__ __align__(16) __half dyn[];
    const __half *Ahi, *Alo, *Bh;
    if (mode == 2) { Ahi = d_x1hi; Alo = d_x1lo; Bh = d_W1hi; }
    else           { Ahi = d_x2hi; Alo = d_x2lo; Bh = d_W2hi; }

    const int tid = threadIdx.x;
    const int lane = tid & 31, w = tid >> 5;
    const int mw = w & 3, nw = w >> 2;   // 4 x 4 warp grid
    const int n0 = blockIdx.x * 32;
    const int nst = K / KC;

#define LSTAGE(k0_, slot_) do {                                                       \
    __half* _sl = dyn + (slot_) * LSLOT;                                              \
    _Pragma("unroll")                                                                 \
    for (int _i = 0; _i < 2; _i++) {                                                  \
        int _c = tid + _i * 512;                                                      \
        int _arr = _c >> 9, _rem = _c & 511;                                          \
        int _row = _rem >> 3, _ch = _rem & 7;                                         \
        const __half* _src = (_arr ? Alo : Ahi) + (size_t)_row * lda + (k0_) + _ch * 8; \
        cpasync16(_sl + _arr * AOFF_LO + _row * APE + _ch * 8, _src);                 \
    }                                                                                 \
    if (tid < 256) {                                                                  \
        int _row = tid >> 3, _ch = tid & 7;                                           \
        cpasync16(_sl + BOFF + _row * APE + _ch * 8,                                  \
                  Bh + (size_t)(n0 + _row) * K + (k0_) + _ch * 8);                    \
    }                                                                                 \
} while (0)

#pragma unroll
    for (int p = 0; p < LNSTG - 1; p++) {
        if (p < nst) LSTAGE(p * KC, p);
        CP_COMMIT();
    }

    const int ar = mw * 16 + (lane & 15);
    const int ac = (lane >> 4) * 8;
    const int t16 = lane & 15;
    const int br = nw * 8 + (t16 & 7);
    const int bc = (t16 >> 3) * 8;

    float ch[4] = {0.f, 0.f, 0.f, 0.f};
    float cl[4] = {0.f, 0.f, 0.f, 0.f};

    int rd = 0;
    for (int s = 0; s < nst; s++) {
        asm volatile("cp.async.wait_group %0;" :: "n"(LNSTG - 2) : "memory");
        __syncthreads();
        int wrslot = rd - 1;
        if (wrslot < 0) wrslot += LNSTG;
        if (s + LNSTG - 1 < nst) LSTAGE((s + LNSTG - 1) * KC, wrslot);
        CP_COMMIT();

        const __half* sl = dyn + rd * LSLOT;
#pragma unroll
        for (int kh = 0; kh < 4; kh++) {
            uint32_t ah[4], al[4], bh[2];
            ldsm_x4(ah, sl + ar * APE + kh * 16 + ac);
            ldsm_x4(al, sl + AOFF_LO + ar * APE + kh * 16 + ac);
            ldsm_x2(bh, sl + BOFF + br * APE + kh * 16 + bc);
            mma16816(ch, ah, bh);
            mma16816(cl, al, bh);
        }
        rd++;
        if (rd == LNSTG) rd = 0;
    }
    asm volatile("cp.async.wait_group 0;" ::: "memory");
    __syncthreads();

    // ---- fused LSTM cell epilogue ----
    float* Gs = (float*)dyn;  // [64][36]
    const float* add1 = (mode == 2) ? d_base1p : d_bias2p;
    const float* add2 = d_wc + (size_t)t * Bsz * G4P;
    float* cbuf = (mode == 2) ? d_c1 : d_c2;
#pragma unroll
    for (int i = 0; i < 4; i++) {
        int m = mw * 16 + (lane >> 2) + ((i >> 1) << 3);
        int nl = nw * 8 + ((lane & 3) << 1) + (i & 1);
        int n = n0 + nl;
        float addv = (mode == 2)
                         ? (add1[(size_t)m * G4P + n] + add2[(size_t)m * G4P + n])
                         : add1[n];
        Gs[m * 36 + nl] = ch[i] + cl[i] + addv;
    }
    __syncthreads();
    {
        int p = tid;  // 512 = Bsz * 8
        int b = p >> 3, jl = p & 7;
        int j = (n0 >> 2) + jl;
        if (j < DL) {
            float ig = Gs[b * 36 + jl * 4 + 0];
            float fg = Gs[b * 36 + jl * 4 + 1];
            float gg = Gs[b * 36 + jl * 4 + 2];
            float og = Gs[b * 36 + jl * 4 + 3];
            float cn = sigf(fg) * cbuf[b * DL + j] + sigf(ig) * tanhf(gg);
            float h = sigf(og) * tanhf(cn);
            cbuf[b * DL + j] = cn;
            __half hh, hl;
            split1(h, hh, hl);
            if (mode == 2) {
                d_x2hi[(size_t)b * K2P + j] = hh;
                d_x2lo[(size_t)b * K2P + j] = hl;
                d_x2hi[(size_t)b * K2P + 3048 + j] = d_x1hi[(size_t)b * K1P + j];
                d_x2lo[(size_t)b * K2P + 3048 + j] = d_x1lo[(size_t)b * K1P + j];
            } else {
                d_x1hi[(size_t)b * K1P + j] = hh;
                d_x1lo[(size_t)b * K1P + j] = hl;
                d_x1hi[(size_t)b * K1P + DL + j] = d_x2hi[(size_t)b * K2P + j];
                d_x1lo[(size_t)b * K1P + DL + j] = d_x2lo[(size_t)b * K2P + j];
                size_t ho = ((size_t)t * Bsz + b) * KEP + j;
                d_h2hi[ho] = hh;
                d_h2lo[ho] = hl;
            }
        }
    }
#undef LSTAGE
}

// ---------------- wide batch GEMMs: wc + img_emb + base1p fused ----------------
__global__ void __launch_bounds__(256) mma_dual() {
    extern __shared__ __align__(16) __half dyn[];
    int by = blockIdx.y, bx = blockIdx.x;
    if (by < NSTEP) {
        gemm_core<8, 3>(dyn, KEP, 0, d_embhi, d_emblo, d_Wehi, KEP,
                        (const float*)0, d_wc, G4P, by * 64, bx * 128);
    } else if (by < NSTEP + (NF * Bsz) / 64) {
        if (bx >= DATT / 128) return;
        gemm_core<8, 3>(dyn, DIMG, 0, d_feathi, d_featlo, d_Waihi, DIMG,
                        (const float*)0, d_imgemb, DATT, (by - NSTEP) * 64, bx * 128);
    } else {
        gemm_core<8, 3>(dyn, DIMG, 4, d_vmhi, d_vmlo, d_W1vhi, DIMG,
                        (const float*)0, d_base1p, G4P, 0, bx * 128);
    }
}

__global__ void __launch_bounds__(256) mma_wp(const float* __restrict__ bias,
                                              float* __restrict__ out) {
    extern __shared__ __align__(16) __half dyn[];
    gemm_core<8, 3>(dyn, KEP, 1, d_h2hi, d_h2lo, d_Wphi, KEP,
                    bias, out, 0, blockIdx.y * 64, blockIdx.x * 128);
}

// ---------------- fused precompute ----------------
#define C0  2097152
#define C1  6291456
#define C2  7340032
#define C3  9895936
#define C4  10158080
#define C4V 12255232
#define C5  13434880
#define C6  13565952
#define C7  13570048
#define CT  13574144
__global__ void k_prep(const float* __restrict__ W1_ih, const float* __restrict__ W1_hh,
                       const float* __restrict__ W2_ih, const float* __restrict__ W2_hh,
                       const float* __restrict__ Wp, const float* __restrict__ Wa_img,
                       const float* __restrict__ feats,
                       const float* __restrict__ b1_ih, const float* __restrict__ b1_hh,
                       const float* __restrict__ b2_ih, const float* __restrict__ b2_hh) {
    int gi = blockIdx.x * 256 + threadIdx.x;
    if (gi >= CT) return;
    if (gi < C4V) {
        const float* Wih;
        const float* Whh = (const float*)0;
        int ihld = 0, splitcol = 0, Kreal, KP, Nvalid = 0;
        __half* dsthi;
        int c, n, k;
        int kind;  // 0 gates, 1 plain, 2 w1v
        if (gi < C0) {
            c = gi; n = c >> 9; k = (c & 511) << 2;
            Wih = W1_ih; Whh = W1_hh; ihld = 4048; splitcol = 1000; Kreal = 2000; KP = 2048;
            dsthi = d_W1hi; kind = 0;
        } else if (gi < C1) {
            c = gi - C0; n = c >> 10; k = (c & 1023) << 2;
            Wih = W2_ih; Whh = W2_hh; ihld = 3048; splitcol = 3048; Kreal = 4048; KP = 4096;
            dsthi = d_W2hi; kind = 0;
        } else if (gi < C2) {
            c = gi - C1; n = c >> 8; k = (c & 255) << 2;
            Wih = W1_ih + 3048; Whh = W1_hh; ihld = 4048; splitcol = 1024; Kreal = 1000;
            KP = 1024; dsthi = d_Wehi; kind = 0;
        } else if (gi < C3) {
            c = gi - C2; n = c >> 8; k = (c & 255) << 2;
            Wih = Wp; Kreal = 1000; KP = 1024; dsthi = d_Wphi; kind = 1;
            ihld = 1000; Nvalid = DICT;
        } else if (gi < C4) {
            c = gi - C3; n = c >> 9; k = (c & 511) << 2;
            Wih = Wa_img; Kreal = 2048; KP = 2048; dsthi = d_Waihi; kind = 1;
            ihld = 2048; Nvalid = DATT;
        } else {
            c = gi - C4; n = c >> 9; k = (c & 511) << 2;
            Wih = W1_ih; Kreal = 2048; KP = 2048; dsthi = d_W1vhi; kind = 2;
            ihld = 4048;
        }
        float4 v = make_float4(0.f, 0.f, 0.f, 0.f);
        if (kind == 0) {
            int j = n >> 2, g = n & 3;
            if (j < DL && k < Kreal) {
                int r = g * DL + j;
                v = (k < splitcol) ? *(const float4*)&Wih[(size_t)r * ihld + k]
                                   : *(const float4*)&Whh[(size_t)r * DL + (k - splitcol)];
            }
        } else if (kind == 1) {
            if (n < Nvalid && k < Kreal)
                v = *(const float4*)&Wih[(size_t)n * ihld + k];
        } else {
            int j = n >> 2, g = n & 3;
            if (j < DL) {
                int r = g * DL + j;
                v = *(const float4*)&Wih[(size_t)r * ihld + 1000 + k];
            }
        }
        __half2 h0 = __floats2half2_rn(v.x, v.y);
        __half2 h1 = __floats2half2_rn(v.z, v.w);
        *(uint2*)&dsthi[(size_t)n * KP + k] = make_uint2(*(uint32_t*)&h0, *(uint32_t*)&h1);
    } else if (gi < C5) {
        int c = gi - C4V;
        int idx = c << 2;
        float4 v = *(const float4*)&feats[idx];
        __half h0, l0, h1, l1, h2, l2, h3, l3;
        split1(v.x, h0, l0); split1(v.y, h1, l1); split1(v.z, h2, l2); split1(v.w, h3, l3);
        __half2 hh0(h0, h1), hh1(h2, h3), ll0(l0, l1), ll1(l2, l3);
        *(uint2*)&d_feathi[idx] = make_uint2(*(uint32_t*)&hh0, *(uint32_t*)&hh1);
        *(uint2*)&d_featlo[idx] = make_uint2(*(uint32_t*)&ll0, *(uint32_t*)&ll1);
    } else if (gi < C6) {
        int i = gi - C5;
        int b = i / DIMG, f = i % DIMG;
        const float* p = feats + (size_t)b * NF * DIMG + f;
        float s = 0.f;
#pragma unroll
        for (int n = 0; n < NF; n++) s += p[n * DIMG];
        s *= (1.0f / NF);
        __half hi, lo;
        split1(s, hi, lo);
        d_vmhi[i] = hi; d_vmlo[i] = lo;
    } else if (gi < C7) {
        int n = gi - C6;
        int j = n >> 2, g = n & 3;
        d_bias2p[n] = (j < DL) ? (b2_ih[g * DL + j] + b2_hh[g * DL + j]) : 0.f;
    } else {
        int n = gi - C7;
        int j = n >> 2, g = n & 3;
        d_bias1p[n] = (j < DL) ? (b1_ih[g * DL + j] + b1_hh[g * DL + j]) : 0.f;
    }
}

// ---------------- fused state init + word embeddings ----------------
#define MTOT (Bsz * K2P + NSTEP * Bsz * KEP)
__global__ void k_misc(const float* __restrict__ h1_0, const float* __restrict__ c1_0,
                       const float* __restrict__ h2_0, const float* __restrict__ c2_0,
                       const float* __restrict__ W_embed,
                       const int* __restrict__ true_words) {
    int i0 = blockIdx.x * 256 + threadIdx.x;
    if (i0 >= MTOT) return;
    if (i0 < Bsz * K2P) {
        int i = i0;
        int b = i >> 12, j = i & 4095;
        __half hi, lo;
        if (j < DL) {
            split1(h1_0[j], hi, lo);
            d_x2hi[i] = hi; d_x2lo[i] = lo;
        } else if (j >= 3048 && j < 3048 + DL) {
            split1(h2_0[j - 3048], hi, lo);
            d_x2hi[i] = hi; d_x2lo[i] = lo;
        } else if (j >= 4048) {
            d_x2hi[i] = __float2half(0.f); d_x2lo[i] = __float2half(0.f);
        }
        if (j < K1P) {
            float v = 0.f;
            if (j < DL) v = h2_0[j];
            else if (j < 2 * DL) v = h1_0[j - DL];
            split1(v, hi, lo);
            d_x1hi[b * K1P + j] = hi; d_x1lo[b * K1P + j] = lo;
        }
        if (j < DL) {
            d_c1[b * DL + j] = c1_0[j];
            d_c2[b * DL + j] = c2_0[j];
        }
    } else {
        int i = i0 - Bsz * K2P;
        int tb = i >> 10, e = i & 1023;
        float v = 0.f;
        if (e < DL) {
            int t = tb / Bsz, b = tb % Bsz;
            int idx = (t == 0) ? 1 : true_words[b * 20 + t];
            v = W_embed[(size_t)e * DICT + idx];
        }
        __half hi, lo;
        split1(v, hi, lo);
        d_embhi[i] = hi; d_emblo[i] = lo;
    }
}

// ---------------- attention projection: proj[b,a] = h1[b,:] . Wa_h[a,:] ----------------
__global__ void __launch_bounds__(256) attn_proj(const float* __restrict__ Wa_h) {
    __shared__ float Ws[8][64];
    __shared__ float Hs[64][65];
    int a0 = blockIdx.x * 8;
    int tid = threadIdx.x;
    float acc0 = 0.f, acc1 = 0.f;
    for (int k0 = 0; k0 < DL; k0 += 64) {
        for (int i = tid; i < 8 * 64; i += 256) {
            int a = i >> 6, kk = i & 63;
            int gk = k0 + kk;
            Ws[a][kk] = (gk < DL) ? Wa_h[(size_t)(a0 + a) * DL + gk] : 0.f;
        }
        for (int i = tid; i < 64 * 64; i += 256) {
            int bb = i >> 6, kk = i & 63;
            int gk = k0 + kk;
            float hv = 0.f;
            if (gk < DL)
                hv = __half2float(d_x2hi[(size_t)bb * K2P + gk]) +
                     __half2float(d_x2lo[(size_t)bb * K2P + gk]);
            Hs[bb][kk] = hv;
        }
        __syncthreads();
        {
            int a = tid >> 6, bb = tid & 63;
            float s = 0.f;
#pragma unroll
            for (int kk = 0; kk < 64; kk++) s += Ws[a][kk] * Hs[bb][kk];
            acc0 += s;
        }
        {
            int o = tid + 256;
            int a = o >> 6, bb = o & 63;
            float s = 0.f;
#pragma unroll
            for (int kk = 0; kk < 64; kk++) s += Ws[a][kk] * Hs[bb][kk];
            acc1 += s;
        }
        __syncthreads();
    }
    {
        int a = tid >> 6, bb = tid & 63;
        d_proj[bb * DATT + a0 + a] = acc0;
    }
    {
        int o = tid + 256;
        int a = o >> 6, bb = o & 63;
        d_proj[bb * DATT + a0 + a] = acc1;
    }
}

// ---------------- attention softmax (no feats read): probs[b][n] ----------------
__global__ void __launch_bounds__(256) attn_sm(const float* __restrict__ wa,
                                               const float* __restrict__ ba) {
    __shared__ float proj_s[DATT];
    __shared__ float ls[NF];
    int b = blockIdx.x;
    int tid = threadIdx.x;
    int w = tid >> 5, lane = tid & 31;

    proj_s[tid] = d_proj[b * DATT + tid];
    proj_s[tid + 256] = d_proj[b * DATT + tid + 256];
    __syncthreads();

    for (int n = w; n < NF; n += 8) {
        const float* ie = d_imgemb + ((size_t)b * NF + n) * DATT;
        float s = 0.f;
        for (int a = lane; a < DATT; a += 32)
            s += tanhf(ie[a] + proj_s[a]) * wa[a];
#pragma unroll
        for (int off = 16; off; off >>= 1) s += __shfl_down_sync(0xffffffffu, s, off);
        if (lane == 0) ls[n] = s + ba[0];
    }
    __syncthreads();
    if (tid == 0) {
        float mx = -1e30f;
        for (int n = 0; n < NF; n++) mx = fmaxf(mx, ls[n]);
        float sum = 0.f;
        for (int n = 0; n < NF; n++) {
            float e = expf(ls[n] - mx);
            ls[n] = e;
            sum += e;
        }
        float inv = 1.f / sum;
        for (int n = 0; n < NF; n++) d_attnp[b * 64 + n] = ls[n] * inv;
    }
}

// ---------------- v_hat: 512 blocks, coalesced feats reads, split into x2 ----------
__global__ void __launch_bounds__(256) vhat_k(const float* __restrict__ feats) {
    __shared__ float ps[NF];
    int b = blockIdx.x;
    int f0 = blockIdx.y * 256;
    int tid = threadIdx.x;
    if (tid < NF) ps[tid] = d_attnp[b * 64 + tid];
    __syncthreads();
    int f = f0 + tid;
    const float* fb = feats + (size_t)b * NF * DIMG + f;
    float s = 0.f;
#pragma unroll
    for (int n = 0; n < NF; n++) s += ps[n] * fb[(size_t)n * DIMG];
    __half hh, hl;
    split1(s, hh, hl);
    d_x2hi[(size_t)b * K2P + DL + f] = hh;
    d_x2lo[(size_t)b * K2P + DL + f] = hl;
}

// ---------------- launch ----------------
extern "C" void kernel_launch(void* const* d_in, const int* in_sizes, int n_in,
                              void* d_out, int out_size) {
    const float* image_feats = (const float*)d_in[0];
    const int* true_words = (const int*)d_in[2];
    const float* W_embed = (const float*)d_in[3];
    const float* W1_ih = (const float*)d_in[4];
    const float* W1_hh = (const float*)d_in[5];
    const float* b1_ih = (const float*)d_in[6];
    const float* b1_hh = (const float*)d_in[7];
    const float* W2_ih = (const float*)d_in[8];
    const float* W2_hh = (const float*)d_in[9];
    const float* b2_ih = (const float*)d_in[10];
    const float* b2_hh = (const float*)d_in[11];
    const float* Wa_img = (const float*)d_in[12];
    const float* Wa_h = (const float*)d_in[13];
    const float* wa = (const float*)d_in[14];
    const float* ba = (const float*)d_in[15];
    const float* Wp = (const float*)d_in[16];
    const float* bp = (const float*)d_in[17];
    const float* h1_0 = (const float*)d_in[18];
    const float* c1_0 = (const float*)d_in[19];
    const float* h2_0 = (const float*)d_in[20];
    const float* c2_0 = (const float*)d_in[21];

    cudaFuncSetAttribute(mma_k, cudaFuncAttributeMaxDynamicSharedMemorySize, SMEM_L);
    cudaFuncSetAttribute(mma_dual, cudaFuncAttributeMaxDynamicSharedMemorySize, SMEM_W);
    cudaFuncSetAttribute(mma_wp, cudaFuncAttributeMaxDynamicSharedMemorySize, SMEM_W);

    // launch 0: fused precompute (all splits + vmean + biases)
    k_prep<<<(CT + 255) / 256, 256>>>(W1_ih, W1_hh, W2_ih, W2_hh, Wp, Wa_img,
                                      image_feats, b1_ih, b1_hh, b2_ih, b2_hh);
    // launch 1: state init + word embeddings
    k_misc<<<(MTOT + 255) / 256, 256>>>(h1_0, c1_0, h2_0, c2_0, W_embed, true_words);
    // launch 2: wc + img_emb + base1p fused (NT=8)
    mma_dual<<<dim3(G4P / 128, NSTEP + (NF * Bsz) / 64 + 1), 256, SMEM_W>>>();

    // ---- recurrent loop ----
    for (int t = 0; t < NSTEP; t++) {
        mma_k<<<dim3(G4P / 32, 1), 512, SMEM_L>>>(K1P, 2, K1P, t);
        attn_proj<<<DATT / 8, 256>>>(Wa_h);
        attn_sm<<<Bsz, 256>>>(wa, ba);
        vhat_k<<<dim3(Bsz, DIMG / 256), 256>>>(image_feats);
        mma_k<<<dim3(G4P / 32, 1), 512, SMEM_L>>>(K2P, 3, K2P, t);
    }

    // ---- final: out[b,t,:] = h2all[t,b,:] @ Wp^T + bp ----
    mma_wp<<<dim3(DICTP / 128, NSTEP), 256, SMEM_W>>>(bp, (float*)d_out);
}